// round 8
// baseline (speedup 1.0000x reference)
#include <cuda_runtime.h>
#include <cuda_fp16.h>
#include <cstdint>
#include <math.h>

#define Hdim 1024
#define Bq 64
#define Sq 512
#define NG 4096                 // 4*H
#define NROWS (Sq*Bq)           // 32768
#define HH (Hdim*Hdim)          // 1048576
#define NCTA 128
#define WH16OFF ((size_t)2*4*HH)

// ---------------- scratch (device globals; no allocations allowed) ----------------
__device__ __half g_W16[(size_t)4 * 4 * HH];        // Wi (2 layers) then Wh (2 layers)
__device__ __half g_x16[(size_t)Bq * Sq * Hdim];    // x converted to half
__device__ __half g_gx16[(size_t)NROWS * NG];       // input-side gate pre-activations (+biases)
__device__ __half g_seq16[(size_t)Sq * Bq * Hdim];  // layer-0 hidden sequence [S][B][H]
__device__ __half g_h16[2][Bq * Hdim];              // recurrent h double buffer (half)
__device__ float g_h[2][Bq * Hdim];                 // final h per layer (fp32)
__device__ float g_c[2][Bq * Hdim];                 // final c per layer (fp32)
__device__ unsigned g_flag[NCTA * 8];               // per-CTA step flags, padded 32B
__device__ unsigned g_qgen[4 * 64];                 // per-quadrant gen, 8 padded copies each

// ---------------- helpers ----------------
__device__ __forceinline__ uint32_t sptr(const void* p) {
    return (uint32_t)__cvta_generic_to_shared(p);
}

__device__ __forceinline__ void mma_f16(float* d, const uint32_t* a, const uint32_t* b) {
    asm volatile(
        "mma.sync.aligned.m16n8k16.row.col.f32.f16.f16.f32 "
        "{%0,%1,%2,%3}, {%4,%5,%6,%7}, {%8,%9}, {%0,%1,%2,%3};\n"
        : "+f"(d[0]), "+f"(d[1]), "+f"(d[2]), "+f"(d[3])
        : "r"(a[0]), "r"(a[1]), "r"(a[2]), "r"(a[3]), "r"(b[0]), "r"(b[1]));
}

__device__ __forceinline__ void ldm_x4(uint32_t* r, uint32_t addr) {
    asm volatile("ldmatrix.sync.aligned.m8n8.x4.shared.b16 {%0,%1,%2,%3}, [%4];"
        : "=r"(r[0]), "=r"(r[1]), "=r"(r[2]), "=r"(r[3]) : "r"(addr));
}
__device__ __forceinline__ void ldm_x4t(uint32_t* r, uint32_t addr) {
    asm volatile("ldmatrix.sync.aligned.m8n8.x4.trans.shared.b16 {%0,%1,%2,%3}, [%4];"
        : "=r"(r[0]), "=r"(r[1]), "=r"(r[2]), "=r"(r[3]) : "r"(addr));
}

__device__ __forceinline__ void cp16(void* dst, const void* src) {
    uint32_t d = sptr(dst);
    asm volatile("cp.async.cg.shared.global [%0], [%1], 16;\n" :: "r"(d), "l"(src));
}
#define CP_COMMIT() asm volatile("cp.async.commit_group;\n")
#define CPW(n) asm volatile("cp.async.wait_group %0;\n" :: "n"(n))

__device__ __forceinline__ void barn(int id, int cnt) {
    asm volatile("bar.sync %0, %1;" :: "r"(id), "r"(cnt) : "memory");
}

// ---------------- prep: convert weights and x to half ----------------
__global__ void prep_kernel(const float* __restrict__ Wi, const float* __restrict__ Wh,
                            const float* __restrict__ x) {
    size_t i = (size_t)blockIdx.x * 256 + threadIdx.x;
    if (i < (size_t)2 * 4 * HH) {
        g_W16[i] = __float2half(Wi[i]);
        g_W16[WH16OFF + i] = __float2half(Wh[i]);
    }
    if (i < (size_t)Bq * Sq * Hdim) g_x16[i] = __float2half(x[i]);
}

// ---------------- projection GEMM: gx16 = X @ Wi[l] + (bi[l]+bh[l]) ----------------
__global__ void __launch_bounds__(256, 3)
proj_kernel(int layer, const float* __restrict__ bi_all, const float* __restrict__ bh_all) {
    __shared__ __half As[2][128 * 40];
    __shared__ __half Bs[2][32 * 72];

    const int tid = threadIdx.x, lane = tid & 31, w = tid >> 5;
    const int g = lane >> 2, t4 = lane & 3;
    const int wm = w & 3, wn = w >> 2;
    const int rbase = blockIdx.y * 128;
    const int n0 = blockIdx.x * 64;
    const int gate = n0 >> 10, h0 = n0 & 1023;

    const __half* Wp = g_W16 + (size_t)layer * 4 * HH + (size_t)gate * HH + h0;
    const __half* Ap = (layer == 0) ? g_x16 : g_seq16;

    float acc[2][4][4];
#pragma unroll
    for (int a = 0; a < 2; a++)
#pragma unroll
        for (int b = 0; b < 4; b++)
#pragma unroll
            for (int c = 0; c < 4; c++) acc[a][b][c] = 0.f;

    auto loadA = [&](int buf, int kb) {
#pragma unroll
        for (int o = 0; o < 2; o++) {
            int idx = tid + o * 256;
            int r = idx >> 2, c = idx & 3;
            int grow = rbase + r;
            const __half* src;
            if (layer == 0) {
                int b = grow & 63, s = grow >> 6;
                src = Ap + ((size_t)b * Sq + s) * Hdim + kb + c * 8;
            } else {
                src = Ap + (size_t)grow * Hdim + kb + c * 8;
            }
            cp16(&As[buf][r * 40 + c * 8], src);
        }
    };
    auto loadB = [&](int buf, int kb) {
        int r = tid >> 3, c = tid & 7;
        cp16(&Bs[buf][r * 72 + c * 8], Wp + (size_t)(kb + r) * Hdim + c * 8);
    };

    loadA(0, 0); loadB(0, 0); CP_COMMIT();

    const int arow = lane & 15, aoff = (lane & 16) ? 8 : 0;
    const int NKC = Hdim / 32;  // 32
    for (int kc = 0; kc < NKC; kc++) {
        int cur = kc & 1;
        CPW(0);
        __syncthreads();
        if (kc + 1 < NKC) {
            loadA(cur ^ 1, (kc + 1) * 32);
            loadB(cur ^ 1, (kc + 1) * 32);
            CP_COMMIT();
        }
        const __half* Ab = As[cur];
        const __half* Bb = Bs[cur];
#pragma unroll
        for (int ks2 = 0; ks2 < 2; ks2++) {
            uint32_t af[2][4], bf[2][4];
#pragma unroll
            for (int mt = 0; mt < 2; mt++)
                ldm_x4(af[mt], sptr(Ab + (wm * 32 + mt * 16 + arow) * 40 + ks2 * 16 + aoff));
#pragma unroll
            for (int nt = 0; nt < 2; nt++)
                ldm_x4t(bf[nt], sptr(Bb + (ks2 * 16 + arow) * 72 + wn * 32 + nt * 16 + aoff));
#pragma unroll
            for (int mt = 0; mt < 2; mt++)
#pragma unroll
                for (int q = 0; q < 4; q++)
                    mma_f16(acc[mt][q], af[mt], &bf[q >> 1][(q & 1) * 2]);
        }
    }

    const float* bi = bi_all + layer * NG;
    const float* bh = bh_all + layer * NG;
#pragma unroll
    for (int mt = 0; mt < 2; mt++) {
        int r0 = rbase + wm * 32 + mt * 16 + g;
#pragma unroll
        for (int q = 0; q < 4; q++) {
            int ng = n0 + wn * 32 + q * 8 + 2 * t4;
            float b0 = bi[ng] + bh[ng];
            float b1 = bi[ng + 1] + bh[ng + 1];
            *reinterpret_cast<__half2*>(g_gx16 + (size_t)r0 * NG + ng) =
                __floats2half2_rn(acc[mt][q][0] + b0, acc[mt][q][1] + b1);
            *reinterpret_cast<__half2*>(g_gx16 + (size_t)(r0 + 8) * NG + ng) =
                __floats2half2_rn(acc[mt][q][2] + b0, acc[mt][q][3] + b1);
        }
    }
}

// ---------------- persistent recurrent kernel: quadrant-pipelined exchange ----------------
// 128 CTAs x 512 threads (4 warpgroups). K split into 4 quadrants of 256 cols
// (32 producer CTAs each). CTA0's wg q relays quadrant q's flags into g_qgen[q];
// every CTA's wg q waits gen-q, stages quadrant q, and block barrier (q+1) gates
// MMA on quadrant q — so flag/data latency of later quadrants hides behind
// compute on earlier ones.
__global__ void __launch_bounds__(512, 1)
recur_kernel(int layer) {
    extern __shared__ unsigned char smraw[];
    __half* Bs  = (__half*)smraw;                       // [1024][40]  Wh slice
    __half* As  = (__half*)(smraw + 81920);             // [64][1032]  full h staging
    float*  pre = (float*)(smraw + 81920 + 132096);     // [64][33]    pre-activations
    __half* gxs = (__half*)((char*)pre + 8448);         // [64][32]    gx staging
    float*  cs  = (float*)((char*)gxs + 4096);          // [512]       c-state

    const int tid = threadIdx.x, cta = blockIdx.x;
    const int lane = tid & 31, w = tid >> 5;
    const int g = lane >> 2, t4 = lane & 3;
    const int wm = w & 3, wn = w >> 2;     // warp grid 4(M) x 4(N), warp tile 16x8
    const int n0 = cta * 8;
    const int arow = lane & 15, aoff = (lane & 16) ? 8 : 0;
    const int wgid = tid >> 7;             // warpgroup 0..3 == quadrant owned
    const int wtid = tid & 127;

    unsigned F0 = *(volatile unsigned*)&g_flag[cta * 8];   // all flags equal at entry

    // load Wh slice into SMEM: Bs[k][gate*8+j]
    const __half* Whp = g_W16 + WH16OFF + (size_t)layer * 4 * HH;
    for (int i = tid; i < 4096; i += 512) {
        int k = i >> 2, gt = i & 3;
        cp16(&Bs[k * 40 + gt * 8], Whp + (size_t)gt * HH + (size_t)k * Hdim + n0);
    }
    CP_COMMIT();

    cs[tid] = 0.f;
    if (tid < 64)
        *reinterpret_cast<uint4*>(&g_h16[0][tid * Hdim + n0]) = make_uint4(0, 0, 0, 0);
    __threadfence();
    __syncthreads();
    if (tid == 0) *(volatile unsigned*)&g_flag[cta * 8] = F0 + 1;

    for (int t = 0; t < Sq; t++) {
        const unsigned need = F0 + 1 + t;

        // gx prefetch (independent of h), own commit group
        if (tid < 256) {
            int r = tid >> 2, gt = tid & 3;
            cp16(&gxs[r * 32 + gt * 8],
                 g_gx16 + ((size_t)(t * 64 + r)) * NG + (size_t)gt * 1024 + n0);
        }
        CP_COMMIT();

        // per-quadrant rendezvous (wg q handles quadrant q)
        if (cta == 0) {
            if (wtid < 32) {
                volatile unsigned* f = &g_flag[(wgid * 32 + wtid) * 8];
                if ((int)(*f - need) < 0) {
                    do { __nanosleep(32); } while ((int)(*f - need) < 0);
                }
            }
            barn(5 + wgid, 128);
            if (wtid < 8) {
                __threadfence();
                *(volatile unsigned*)&g_qgen[wgid * 64 + wtid * 8] = need;
            }
        } else {
            if (wtid == 0) {
                volatile unsigned* gp = &g_qgen[wgid * 64 + (cta & 7) * 8];
                if ((int)(*gp - need) < 0) {
                    do { __nanosleep(32); } while ((int)(*gp - need) < 0);
                }
            }
            barn(5 + wgid, 128);
        }

        const __half* curh = g_h16[t & 1];
        __half* nxth = g_h16[(t + 1) & 1];

        // stage own quadrant: 64 rows x 256 cols = 32KB, 16 cp16 per thread
#pragma unroll
        for (int i = 0; i < 16; i++) {
            int idx = i * 128 + wtid;
            int r = idx >> 5, seg = idx & 31;
            cp16(&As[r * 1032 + wgid * 256 + seg * 8],
                 curh + (size_t)r * Hdim + wgid * 256 + seg * 8);
        }
        CP_COMMIT();
        CPW(0);   // drains own groups (incl. gx for tid<256, Wh on first step)

        float accE[4], accO[4];
#pragma unroll
        for (int a = 0; a < 4; a++) { accE[a] = 0.f; accO[a] = 0.f; }

        // consume quadrants in order; block barrier (q+1) gates each
#pragma unroll
        for (int q = 0; q < 4; q++) {
            barn(q + 1, 512);
#pragma unroll
            for (int ks = 0; ks < 8; ks++) {
                int kb = q * 256 + ks * 32;
                uint32_t afE[4], afO[4], bf[4];
                ldm_x4(afE, sptr(As + (wm * 16 + arow) * 1032 + kb + aoff));
                ldm_x4(afO, sptr(As + (wm * 16 + arow) * 1032 + kb + 16 + aoff));
                ldm_x4t(bf, sptr(Bs + (kb + lane) * 40 + wn * 8));
                mma_f16(accE, afE, bf);
                mma_f16(accO, afO, bf + 2);
            }
        }

        // stage pre-activations (sum the two chains)
        {
            int col = wn * 8 + 2 * t4;
            pre[(wm * 16 + g) * 33 + col]         = accE[0] + accO[0];
            pre[(wm * 16 + g) * 33 + col + 1]     = accE[1] + accO[1];
            pre[(wm * 16 + g + 8) * 33 + col]     = accE[2] + accO[2];
            pre[(wm * 16 + g + 8) * 33 + col + 1] = accE[3] + accO[3];
        }
        __syncthreads();

        // fused cell update (1 element per thread)
        {
            int p = tid;
            int b = p >> 3, j = p & 7;
            float v0 = pre[b * 33 + j]      + __half2float(gxs[b * 32 + j]);
            float v1 = pre[b * 33 + 8 + j]  + __half2float(gxs[b * 32 + 8 + j]);
            float v2 = pre[b * 33 + 16 + j] + __half2float(gxs[b * 32 + 16 + j]);
            float v3 = pre[b * 33 + 24 + j] + __half2float(gxs[b * 32 + 24 + j]);
            float i_ = 1.f / (1.f + expf(-v0));
            float f_ = 1.f / (1.f + expf(-v1));
            float gg = tanhf(v2);
            float o_ = 1.f / (1.f + expf(-v3));
            float cn = f_ * cs[p] + i_ * gg;
            float hn = o_ * tanhf(cn);
            cs[p] = cn;
            __half hr = __float2half(hn);
            nxth[b * Hdim + n0 + j] = hr;
            if (layer == 0) g_seq16[((size_t)t * 64 + b) * Hdim + n0 + j] = hr;
            if (t == Sq - 1) {
                g_h[layer][b * Hdim + n0 + j] = hn;
                g_c[layer][b * Hdim + n0 + j] = cn;
            }
        }
        __threadfence();
        __syncthreads();
        if (tid == 0) *(volatile unsigned*)&g_flag[cta * 8] = F0 + 2 + t;
    }
}

// ---------------- finalize: pack output tuple (seq_last, h_n[2], c_n[2]) ----------------
__global__ void finalize_kernel(float* __restrict__ out, int out_size) {
    int idx = blockIdx.x * 256 + threadIdx.x;  // 0..65535
    const int N1 = Bq * Hdim;
    if (idx + 0 * N1 < out_size) out[idx]          = g_h[1][idx];
    if (idx + 1 * N1 < out_size) out[idx + N1]     = g_h[0][idx];
    if (idx + 2 * N1 < out_size) out[idx + 2 * N1] = g_h[1][idx];
    if (idx + 3 * N1 < out_size) out[idx + 3 * N1] = g_c[0][idx];
    if (idx + 4 * N1 < out_size) out[idx + 4 * N1] = g_c[1][idx];
}

// ---------------- launch: 6 graph nodes total ----------------
extern "C" void kernel_launch(void* const* d_in, const int* in_sizes, int n_in,
                              void* d_out, int out_size) {
    const float* x  = (const float*)d_in[0];
    const float* Wi = (const float*)d_in[1];
    const float* bi = (const float*)d_in[2];
    const float* Wh = (const float*)d_in[3];
    const float* bh = (const float*)d_in[4];
    float* out = (float*)d_out;
    (void)in_sizes; (void)n_in;

    const int recur_smem = 81920 + 132096 + 8448 + 4096 + 2048;  // 228608 B
    cudaFuncSetAttribute(recur_kernel, cudaFuncAttributeMaxDynamicSharedMemorySize,
                         recur_smem);

    prep_kernel<<<131072, 256>>>(Wi, Wh, x);
    for (int l = 0; l < 2; l++) {
        proj_kernel<<<dim3(NG / 64, NROWS / 128), 256>>>(l, bi, bh);
        recur_kernel<<<NCTA, 512, recur_smem>>>(l);
    }
    finalize_kernel<<<256, 256>>>(out, out_size);
}

// round 9
// speedup vs baseline: 1.1927x; 1.1927x over previous
#include <cuda_runtime.h>
#include <cuda_fp16.h>
#include <cstdint>
#include <math.h>

#define Hdim 1024
#define Bq 64
#define Sq 512
#define NG 4096                 // 4*H
#define NROWS (Sq*Bq)           // 32768
#define HH (Hdim*Hdim)          // 1048576
#define NCTA 128
#define WH16OFF ((size_t)2*4*HH)

// ---------------- scratch (device globals; no allocations allowed) ----------------
__device__ __half g_W16[(size_t)4 * 4 * HH];        // Wi (2 layers) then Wh (2 layers)
__device__ __half g_x16[(size_t)Bq * Sq * Hdim];    // x converted to half
__device__ __half g_gx16[(size_t)NROWS * NG];       // gate pre-activations, [row][cta][gate][8]
__device__ __half g_seq16[(size_t)Sq * Bq * Hdim];  // layer-0 hidden sequence [S][B][H]
__device__ __half g_h16[2][Bq * Hdim];              // recurrent h double buffer (half)
__device__ float g_h[2][Bq * Hdim];                 // final h per layer (fp32)
__device__ float g_c[2][Bq * Hdim];                 // final c per layer (fp32)
__device__ unsigned g_flag[NCTA * 8];               // per-CTA step flags, padded 32B
__device__ unsigned g_qgen[4 * 64];                 // per-quadrant gen, 8 padded copies each

// ---------------- helpers ----------------
__device__ __forceinline__ uint32_t sptr(const void* p) {
    return (uint32_t)__cvta_generic_to_shared(p);
}

__device__ __forceinline__ void mma_f16(float* d, const uint32_t* a, const uint32_t* b) {
    asm volatile(
        "mma.sync.aligned.m16n8k16.row.col.f32.f16.f16.f32 "
        "{%0,%1,%2,%3}, {%4,%5,%6,%7}, {%8,%9}, {%0,%1,%2,%3};\n"
        : "+f"(d[0]), "+f"(d[1]), "+f"(d[2]), "+f"(d[3])
        : "r"(a[0]), "r"(a[1]), "r"(a[2]), "r"(a[3]), "r"(b[0]), "r"(b[1]));
}

__device__ __forceinline__ void ldm_x4(uint32_t* r, uint32_t addr) {
    asm volatile("ldmatrix.sync.aligned.m8n8.x4.shared.b16 {%0,%1,%2,%3}, [%4];"
        : "=r"(r[0]), "=r"(r[1]), "=r"(r[2]), "=r"(r[3]) : "r"(addr));
}
__device__ __forceinline__ void ldm_x4t(uint32_t* r, uint32_t addr) {
    asm volatile("ldmatrix.sync.aligned.m8n8.x4.trans.shared.b16 {%0,%1,%2,%3}, [%4];"
        : "=r"(r[0]), "=r"(r[1]), "=r"(r[2]), "=r"(r[3]) : "r"(addr));
}

__device__ __forceinline__ void cp16(void* dst, const void* src) {
    uint32_t d = sptr(dst);
    asm volatile("cp.async.cg.shared.global [%0], [%1], 16;\n" :: "r"(d), "l"(src));
}
#define CP_COMMIT() asm volatile("cp.async.commit_group;\n")
#define CPW(n) asm volatile("cp.async.wait_group %0;\n" :: "n"(n))

__device__ __forceinline__ void barn(int id, int cnt) {
    asm volatile("bar.sync %0, %1;" :: "r"(id), "r"(cnt) : "memory");
}

// ---------------- prep: convert weights and x to half ----------------
__global__ void prep_kernel(const float* __restrict__ Wi, const float* __restrict__ Wh,
                            const float* __restrict__ x) {
    size_t i = (size_t)blockIdx.x * 256 + threadIdx.x;
    if (i < (size_t)2 * 4 * HH) {
        g_W16[i] = __float2half(Wi[i]);
        g_W16[WH16OFF + i] = __float2half(Wh[i]);
    }
    if (i < (size_t)Bq * Sq * Hdim) g_x16[i] = __float2half(x[i]);
}

// ---------------- projection GEMM: gx16 = X @ Wi[l] + (bi[l]+bh[l]) ----------------
// Output layout permuted for the recurrence: gx[row][cta][gate][j] with cta=h>>3, j=h&7.
__global__ void __launch_bounds__(256, 3)
proj_kernel(int layer, const float* __restrict__ bi_all, const float* __restrict__ bh_all) {
    __shared__ __half As[2][128 * 40];
    __shared__ __half Bs[2][32 * 72];

    const int tid = threadIdx.x, lane = tid & 31, w = tid >> 5;
    const int g = lane >> 2, t4 = lane & 3;
    const int wm = w & 3, wn = w >> 2;
    const int rbase = blockIdx.y * 128;
    const int n0 = blockIdx.x * 64;
    const int gate = n0 >> 10, h0 = n0 & 1023;

    const __half* Wp = g_W16 + (size_t)layer * 4 * HH + (size_t)gate * HH + h0;
    const __half* Ap = (layer == 0) ? g_x16 : g_seq16;

    float acc[2][4][4];
#pragma unroll
    for (int a = 0; a < 2; a++)
#pragma unroll
        for (int b = 0; b < 4; b++)
#pragma unroll
            for (int c = 0; c < 4; c++) acc[a][b][c] = 0.f;

    auto loadA = [&](int buf, int kb) {
#pragma unroll
        for (int o = 0; o < 2; o++) {
            int idx = tid + o * 256;
            int r = idx >> 2, c = idx & 3;
            int grow = rbase + r;
            const __half* src;
            if (layer == 0) {
                int b = grow & 63, s = grow >> 6;
                src = Ap + ((size_t)b * Sq + s) * Hdim + kb + c * 8;
            } else {
                src = Ap + (size_t)grow * Hdim + kb + c * 8;
            }
            cp16(&As[buf][r * 40 + c * 8], src);
        }
    };
    auto loadB = [&](int buf, int kb) {
        int r = tid >> 3, c = tid & 7;
        cp16(&Bs[buf][r * 72 + c * 8], Wp + (size_t)(kb + r) * Hdim + c * 8);
    };

    loadA(0, 0); loadB(0, 0); CP_COMMIT();

    const int arow = lane & 15, aoff = (lane & 16) ? 8 : 0;
    const int NKC = Hdim / 32;  // 32
    for (int kc = 0; kc < NKC; kc++) {
        int cur = kc & 1;
        CPW(0);
        __syncthreads();
        if (kc + 1 < NKC) {
            loadA(cur ^ 1, (kc + 1) * 32);
            loadB(cur ^ 1, (kc + 1) * 32);
            CP_COMMIT();
        }
        const __half* Ab = As[cur];
        const __half* Bb = Bs[cur];
#pragma unroll
        for (int ks2 = 0; ks2 < 2; ks2++) {
            uint32_t af[2][4], bf[2][4];
#pragma unroll
            for (int mt = 0; mt < 2; mt++)
                ldm_x4(af[mt], sptr(Ab + (wm * 32 + mt * 16 + arow) * 40 + ks2 * 16 + aoff));
#pragma unroll
            for (int nt = 0; nt < 2; nt++)
                ldm_x4t(bf[nt], sptr(Bb + (ks2 * 16 + arow) * 72 + wn * 32 + nt * 16 + aoff));
#pragma unroll
            for (int mt = 0; mt < 2; mt++)
#pragma unroll
                for (int q = 0; q < 4; q++)
                    mma_f16(acc[mt][q], af[mt], &bf[q >> 1][(q & 1) * 2]);
        }
    }

    const float* bi = bi_all + layer * NG;
    const float* bh = bh_all + layer * NG;
#pragma unroll
    for (int mt = 0; mt < 2; mt++) {
        int r0 = rbase + wm * 32 + mt * 16 + g;
#pragma unroll
        for (int q = 0; q < 4; q++) {
            int ng = n0 + wn * 32 + q * 8 + 2 * t4;           // gate*1024 + h
            int h = ng & 1023;
            int ctao = h >> 3, j = h & 7;
            size_t dst = (size_t)ctao * 32 + gate * 8 + j;    // permuted col
            float b0 = bi[ng] + bh[ng];
            float b1 = bi[ng + 1] + bh[ng + 1];
            *reinterpret_cast<__half2*>(g_gx16 + (size_t)r0 * NG + dst) =
                __floats2half2_rn(acc[mt][q][0] + b0, acc[mt][q][1] + b1);
            *reinterpret_cast<__half2*>(g_gx16 + (size_t)(r0 + 8) * NG + dst) =
                __floats2half2_rn(acc[mt][q][2] + b0, acc[mt][q][3] + b1);
        }
    }
}

// ---------------- persistent recurrent kernel ----------------
// 128 CTAs x 512 threads = 4 warpgroups. CTA owns 32 N cols (8 h-cols x 4 gates).
// wg q owns K-quadrant [256q,256q+256) END-TO-END: waits only its quadrant's gen,
// stages it (4 cp sub-chunks), MMAs its K-slice into private fp32 partials.
// Cross-wg reduction via 2 SMEM buffers, then 1-elem/thread cell update.
__global__ void __launch_bounds__(512, 1)
recur_kernel(int layer) {
    extern __shared__ unsigned char smraw[];
    __half* Bs = (__half*)smraw;                    // [1024][40]  Wh slice       81920B
    __half* As = (__half*)(smraw + 81920);          // [64][1032]  h staging     132096B
    float*  R0 = (float*)(smraw + 214016);          // [64][32]    partial/pre     8192B
    float*  R1 = (float*)(smraw + 222208);          // [64][32]    partial         8192B

    const int tid = threadIdx.x, cta = blockIdx.x;
    const int lane = tid & 31, w = tid >> 5;
    const int g = lane >> 2, t4 = lane & 3;
    const int n0 = cta * 8;
    const int arow = lane & 15, aoff = (lane & 16) ? 8 : 0;
    const int q = w >> 2;                  // warpgroup id = K-quadrant owned
    const int wtid = tid & 127;
    const int wl = w & 3;                  // warp within wg
    const int M0 = (wl & 1) * 32;          // warp grid 2(M) x 2(N), tile 32x16
    const int N0 = (wl >> 1) * 16;

    unsigned F0 = *(volatile unsigned*)&g_flag[cta * 8];

    // Wh slice -> SMEM (cooperative, all threads): Bs[k][gate*8+j]
    const __half* Whp = g_W16 + WH16OFF + (size_t)layer * 4 * HH;
    for (int i = tid; i < 4096; i += 512) {
        int k = i >> 2, gt = i & 3;
        cp16(&Bs[k * 40 + gt * 8], Whp + (size_t)gt * HH + (size_t)k * Hdim + n0);
    }
    CP_COMMIT();
    CPW(0);

    float creg = 0.f;                      // c-state lives in a register
    if (tid < 64)
        *reinterpret_cast<uint4*>(&g_h16[0][tid * Hdim + n0]) = make_uint4(0, 0, 0, 0);
    __threadfence();
    __syncthreads();                       // Wh fully staged + h zeroed
    if (tid == 0) *(volatile unsigned*)&g_flag[cta * 8] = F0 + 1;

    const int ub = tid >> 3, uj = tid & 7; // update-element mapping

    for (int t = 0; t < Sq; t++) {
        const unsigned need = F0 + 1 + t;

        // gx for this thread's update element: 4 early LDGs, hidden by rendezvous
        const __half* gp = g_gx16 + ((size_t)(t * 64 + ub)) * NG + (size_t)cta * 32;
        __half gx0 = gp[uj], gx1 = gp[8 + uj], gx2 = gp[16 + uj], gx3 = gp[24 + uj];

        // per-quadrant rendezvous (wg q fully independent)
        if (cta == 0) {
            if (wtid < 32) {
                volatile unsigned* f = &g_flag[(q * 32 + wtid) * 8];
                if ((int)(*f - need) < 0) {
                    do { __nanosleep(32); } while ((int)(*f - need) < 0);
                }
            }
            barn(5 + q, 128);
            if (wtid < 8) {
                __threadfence();
                *(volatile unsigned*)&g_qgen[q * 64 + wtid * 8] = need;
            }
        } else {
            if (wtid == 0) {
                volatile unsigned* gpp = &g_qgen[q * 64 + (cta & 7) * 8];
                if ((int)(*gpp - need) < 0) {
                    do { __nanosleep(32); } while ((int)(*gpp - need) < 0);
                }
            }
        }
        barn(1 + q, 128);                  // wg-wide: quadrant q's h is published

        const __half* curh = g_h16[t & 1];
        __half* nxth = g_h16[(t + 1) & 1];

        // stage own quadrant in 4 sub-chunks of 64 cols (4 cp groups)
#pragma unroll
        for (int s = 0; s < 4; s++) {
            int colb = q * 256 + s * 64;
#pragma unroll
            for (int i = 0; i < 4; i++) {
                int idx = i * 128 + wtid;          // 0..511
                int r = idx >> 3, seg = idx & 7;
                cp16(&As[r * 1032 + colb + seg * 8],
                     curh + (size_t)r * Hdim + colb + seg * 8);
            }
            CP_COMMIT();
        }

        float accE[2][2][4], accO[2][2][4];
#pragma unroll
        for (int a = 0; a < 2; a++)
#pragma unroll
            for (int b = 0; b < 2; b++)
#pragma unroll
                for (int c = 0; c < 4; c++) { accE[a][b][c] = 0.f; accO[a][b][c] = 0.f; }

        // consume sub-chunks as they land (pipelined within the wg)
#pragma unroll
        for (int s = 0; s < 4; s++) {
            switch (3 - s) { case 3: CPW(3); break; case 2: CPW(2); break;
                             case 1: CPW(1); break; default: CPW(0); break; }
            barn(1 + q, 128);
#pragma unroll
            for (int kk = 0; kk < 2; kk++) {
                int kbase = q * 256 + s * 64 + kk * 32;
                uint32_t afE[2][4], afO[2][4], bf[2][4];
#pragma unroll
                for (int mi = 0; mi < 2; mi++) {
                    ldm_x4(afE[mi], sptr(As + (M0 + mi * 16 + arow) * 1032 + kbase + aoff));
                    ldm_x4(afO[mi], sptr(As + (M0 + mi * 16 + arow) * 1032 + kbase + 16 + aoff));
                }
#pragma unroll
                for (int nf = 0; nf < 2; nf++)
                    ldm_x4t(bf[nf], sptr(Bs + (kbase + lane) * 40 + N0 + nf * 8));
#pragma unroll
                for (int mi = 0; mi < 2; mi++)
#pragma unroll
                    for (int nf = 0; nf < 2; nf++) {
                        mma_f16(accE[mi][nf], afE[mi], &bf[nf][0]);
                        mma_f16(accO[mi][nf], afO[mi], &bf[nf][2]);
                    }
            }
        }

        // merge E/O chains -> 16 values; cross-wg tree reduction via R0/R1
        float val[2][2][4];
#pragma unroll
        for (int mi = 0; mi < 2; mi++)
#pragma unroll
            for (int nf = 0; nf < 2; nf++)
#pragma unroll
                for (int c = 0; c < 4; c++)
                    val[mi][nf][c] = accE[mi][nf][c] + accO[mi][nf][c];

        auto slot = [&](int mi, int nf, int c) {
            int row = M0 + mi * 16 + g + ((c >= 2) ? 8 : 0);
            int col = N0 + nf * 8 + 2 * t4 + (c & 1);
            return row * 32 + col;
        };

        if (q == 2) {
#pragma unroll
            for (int mi = 0; mi < 2; mi++)
#pragma unroll
                for (int nf = 0; nf < 2; nf++)
#pragma unroll
                    for (int c = 0; c < 4; c++) R0[slot(mi, nf, c)] = val[mi][nf][c];
        } else if (q == 3) {
#pragma unroll
            for (int mi = 0; mi < 2; mi++)
#pragma unroll
                for (int nf = 0; nf < 2; nf++)
#pragma unroll
                    for (int c = 0; c < 4; c++) R1[slot(mi, nf, c)] = val[mi][nf][c];
        }
        __syncthreads();   // S1
        if (q == 0) {
#pragma unroll
            for (int mi = 0; mi < 2; mi++)
#pragma unroll
                for (int nf = 0; nf < 2; nf++)
#pragma unroll
                    for (int c = 0; c < 4; c++) val[mi][nf][c] += R0[slot(mi, nf, c)];
        } else if (q == 1) {
#pragma unroll
            for (int mi = 0; mi < 2; mi++)
#pragma unroll
                for (int nf = 0; nf < 2; nf++)
#pragma unroll
                    for (int c = 0; c < 4; c++) {
                        val[mi][nf][c] += R1[slot(mi, nf, c)];
                        R1[slot(mi, nf, c)] = val[mi][nf][c];
                    }
        }
        __syncthreads();   // S2
        if (q == 0) {
#pragma unroll
            for (int mi = 0; mi < 2; mi++)
#pragma unroll
                for (int nf = 0; nf < 2; nf++)
#pragma unroll
                    for (int c = 0; c < 4; c++)
                        R0[slot(mi, nf, c)] = val[mi][nf][c] + R1[slot(mi, nf, c)];
        }
        __syncthreads();   // S3: R0 now holds full pre-activations

        // fused cell update (1 element per thread)
        {
            float v0 = R0[ub * 32 + uj]      + __half2float(gx0);
            float v1 = R0[ub * 32 + 8 + uj]  + __half2float(gx1);
            float v2 = R0[ub * 32 + 16 + uj] + __half2float(gx2);
            float v3 = R0[ub * 32 + 24 + uj] + __half2float(gx3);
            float i_ = 1.f / (1.f + expf(-v0));
            float f_ = 1.f / (1.f + expf(-v1));
            float gg = tanhf(v2);
            float o_ = 1.f / (1.f + expf(-v3));
            float cn = f_ * creg + i_ * gg;
            float hn = o_ * tanhf(cn);
            creg = cn;
            __half hr = __float2half(hn);
            nxth[ub * Hdim + n0 + uj] = hr;
            if (layer == 0) g_seq16[((size_t)t * 64 + ub) * Hdim + n0 + uj] = hr;
            if (t == Sq - 1) {
                g_h[layer][ub * Hdim + n0 + uj] = hn;
                g_c[layer][ub * Hdim + n0 + uj] = cn;
            }
        }
        __threadfence();
        __syncthreads();   // S4
        if (tid == 0) *(volatile unsigned*)&g_flag[cta * 8] = F0 + 2 + t;
    }
}

// ---------------- finalize: pack output tuple (seq_last, h_n[2], c_n[2]) ----------------
__global__ void finalize_kernel(float* __restrict__ out, int out_size) {
    int idx = blockIdx.x * 256 + threadIdx.x;  // 0..65535
    const int N1 = Bq * Hdim;
    if (idx + 0 * N1 < out_size) out[idx]          = g_h[1][idx];
    if (idx + 1 * N1 < out_size) out[idx + N1]     = g_h[0][idx];
    if (idx + 2 * N1 < out_size) out[idx + 2 * N1] = g_h[1][idx];
    if (idx + 3 * N1 < out_size) out[idx + 3 * N1] = g_c[0][idx];
    if (idx + 4 * N1 < out_size) out[idx + 4 * N1] = g_c[1][idx];
}

// ---------------- launch: 6 graph nodes total ----------------
extern "C" void kernel_launch(void* const* d_in, const int* in_sizes, int n_in,
                              void* d_out, int out_size) {
    const float* x  = (const float*)d_in[0];
    const float* Wi = (const float*)d_in[1];
    const float* bi = (const float*)d_in[2];
    const float* Wh = (const float*)d_in[3];
    const float* bh = (const float*)d_in[4];
    float* out = (float*)d_out;
    (void)in_sizes; (void)n_in;

    const int recur_smem = 81920 + 132096 + 8192 + 8192;  // 230400 B
    cudaFuncSetAttribute(recur_kernel, cudaFuncAttributeMaxDynamicSharedMemorySize,
                         recur_smem);

    prep_kernel<<<131072, 256>>>(Wi, Wh, x);
    for (int l = 0; l < 2; l++) {
        proj_kernel<<<dim3(NG / 64, NROWS / 128), 256>>>(l, bi, bh);
        recur_kernel<<<NCTA, 512, recur_smem>>>(l);
    }
    finalize_kernel<<<256, 256>>>(out, out_size);
}